// round 5
// baseline (speedup 1.0000x reference)
#include <cuda_runtime.h>

// Fixed shapes
#define B 2
#define D 160
#define H 160
#define W 160
#define NVOX (B * D * H * W)          // 8,192,000
#define HW (H * W)                    // 25,600

#define HSEGS 4
#define HSEG_LEN (H / HSEGS)          // 40
#define A_BLOCKS (B * D * HSEGS)      // 1280
#define A_STEPS (HSEG_LEN + 10)       // 50 = 4*11 + 6

#define K3_SEGS 4
#define K3_SEGLEN (D / K3_SEGS)       // 40
#define K3_BLOCKS (B * H * K3_SEGS)   // 1280
#define K3_STEPS (K3_SEGLEN + 10)     // 50

// SSIM constants (faithful: C1 = K1 / data_range^2)
#define C1F 5.9604644775390625e-10f   // 0.01 / 4096^2
#define C2F 1.7881393432617188e-09f   // 0.03 / 4096^2
#define INV_WIN3 (1.0f / 1331.0f)

__device__ float g_bufB[5 * NVOX];
__device__ float g_l1part[A_BLOCKS];
__device__ float g_ssimpart[K3_BLOCKS];

// ---------------------------------------------------------------------------
// Kernel A: fused W+H box sums (x, y, x^2, y^2, xy) streaming along h.
// Ring of w-filtered rows lives in REGISTERS (static indices via 11-step
// unroll). Zero-padded smem staging rows -> unconditional taps. One barrier
// per row. grid = B*D*HSEGS, 160 threads (one per w).
// ---------------------------------------------------------------------------
#define KA_STEP(TT) { \
    sx[buf][5 + w] = px; sy[buf][5 + w] = py; \
    const bool outl1 = (r >= h0) && (r < h1); \
    { int rn = r + 1; \
      if (rn >= 0 && rn < H) { px = x[pb + rn * W + w]; py = y[pb + rn * W + w]; } \
      else { px = 0.f; py = 0.f; } } \
    __syncthreads(); \
    { const float* __restrict__ rxp = sx[buf]; \
      const float* __restrict__ ryp = sy[buf]; \
      float ax = 0.f, ay = 0.f, axx = 0.f, ayy = 0.f, axy = 0.f; \
      _Pragma("unroll") \
      for (int jj = 0; jj < 11; jj++) { \
          float a = rxp[w + jj], c = ryp[w + jj]; \
          ax += a; ay += c; \
          axx = fmaf(a, a, axx); ayy = fmaf(c, c, ayy); axy = fmaf(a, c, axy); \
      } \
      rg0[TT] = ax; rg1[TT] = ay; rg2[TT] = axx; rg3[TT] = ayy; rg4[TT] = axy; \
      s0 += ax; s1 += ay; s2 += axx; s3 += ayy; s4 += axy; \
      if (outl1) { \
          float dd = fabsf(rxp[5 + w] - ryp[5 + w]); \
          l1acc += (dd < 1.f) ? 0.5f * dd * dd : dd - 0.5f; \
      } } \
    if (t >= 10) { \
        const int hh = h0 + t - 10; \
        const int oi = pb + hh * W + w; \
        g_bufB[0 * NVOX + oi] = s0; \
        g_bufB[1 * NVOX + oi] = s1; \
        g_bufB[2 * NVOX + oi] = s2; \
        g_bufB[3 * NVOX + oi] = s3; \
        g_bufB[4 * NVOX + oi] = s4; \
        s0 -= rg0[(TT + 1) % 11]; s1 -= rg1[(TT + 1) % 11]; \
        s2 -= rg2[(TT + 1) % 11]; s3 -= rg3[(TT + 1) % 11]; \
        s4 -= rg4[(TT + 1) % 11]; \
    } \
    buf ^= 1; r++; t++; }

__global__ __launch_bounds__(W, 4) void kA_wh(const float* __restrict__ x,
                                              const float* __restrict__ y) {
    __shared__ float sx[2][W + 10];
    __shared__ float sy[2][W + 10];

    const int bx = blockIdx.x;
    const int seg = bx % HSEGS;
    const int d = (bx / HSEGS) % D;
    const int b = bx / (HSEGS * D);
    const int w = threadIdx.x;

    const int h0 = seg * HSEG_LEN;
    const int h1 = h0 + HSEG_LEN;
    const int pb = (b * D + d) * HW;

    if (w < 10) {
        int p = (w < 5) ? w : (W + w);
        sx[0][p] = 0.f; sx[1][p] = 0.f;
        sy[0][p] = 0.f; sy[1][p] = 0.f;
    }

    int r = h0 - 5;
    float px = 0.f, py = 0.f;
    if (r >= 0) {
        px = x[pb + r * W + w];
        py = y[pb + r * W + w];
    }
    __syncthreads();

    float s0 = 0.f, s1 = 0.f, s2 = 0.f, s3 = 0.f, s4 = 0.f;
    float l1acc = 0.f;
    float rg0[11], rg1[11], rg2[11], rg3[11], rg4[11];
    int buf = 0;
    int t = 0;

#pragma unroll 1
    for (int tc = 0; tc < 4; tc++) {
        KA_STEP(0) KA_STEP(1) KA_STEP(2) KA_STEP(3) KA_STEP(4) KA_STEP(5)
        KA_STEP(6) KA_STEP(7) KA_STEP(8) KA_STEP(9) KA_STEP(10)
    }
    // tail: steps 44..49, t%11 = 0..5
    KA_STEP(0) KA_STEP(1) KA_STEP(2) KA_STEP(3) KA_STEP(4) KA_STEP(5)

    // deterministic block reduction of l1acc
    __syncthreads();
    float* red = sx[0];
    red[w] = l1acc;
    __syncthreads();
    if (w < 80) red[w] += red[w + 80];
    __syncthreads();
    if (w < 40) red[w] += red[w + 40];
    __syncthreads();
    if (w < 20) red[w] += red[w + 20];
    __syncthreads();
    if (w < 10) red[w] += red[w + 10];
    __syncthreads();
    if (w < 5) red[w] += red[w + 5];
    __syncthreads();
    if (w == 0) {
        g_l1part[bx] = red[0] + red[1] + red[2] + red[3] + red[4];
    }
}
#undef KA_STEP

// ---------------------------------------------------------------------------
// Kernel B: box-sum along D (read-once via register ring) + SSIM + block
// reduction. grid = B*H*K3_SEGS, 160 threads (one per w).
// ---------------------------------------------------------------------------
#define KB_STEP(TT) { \
    float v0 = 0.f, v1 = 0.f, v2 = 0.f, v3 = 0.f, v4 = 0.f; \
    if (r >= 0 && r < D) { \
        const int id = colbase + r * HW; \
        v0 = p0[id]; v1 = p1[id]; v2 = p2[id]; v3 = p3[id]; v4 = p4[id]; \
    } \
    s0 += v0; s1 += v1; s2 += v2; s3 += v3; s4 += v4; \
    rg0[TT] = v0; rg1[TT] = v1; rg2[TT] = v2; rg3[TT] = v3; rg4[TT] = v4; \
    if (t >= 10) { \
        float mux = s0 * INV_WIN3; \
        float muy = s1 * INV_WIN3; \
        float mux2 = mux * mux; \
        float muy2 = muy * muy; \
        float muxy = mux * muy; \
        float sxx = s2 * INV_WIN3 - mux2; \
        float syy = s3 * INV_WIN3 - muy2; \
        float sxy = s4 * INV_WIN3 - muxy; \
        float num = (2.f * muxy + C1F) * (2.f * sxy + C2F); \
        float den = (mux2 + muy2 + C1F) * (sxx + syy + C2F); \
        float ssim = num / (den + 1e-8f); \
        float loss = (1.f - ssim) * 0.5f; \
        acc += fminf(fmaxf(loss, 0.f), 1.f); \
        s0 -= rg0[(TT + 1) % 11]; s1 -= rg1[(TT + 1) % 11]; \
        s2 -= rg2[(TT + 1) % 11]; s3 -= rg3[(TT + 1) % 11]; \
        s4 -= rg4[(TT + 1) % 11]; \
    } \
    r++; t++; }

__global__ __launch_bounds__(W, 4) void kB_dpass_ssim() {
    __shared__ float red[W];

    const int bid = blockIdx.x;
    const int seg = bid % K3_SEGS;
    const int h = (bid / K3_SEGS) % H;
    const int b = bid / (K3_SEGS * H);
    const int w = threadIdx.x;

    const int d0 = seg * K3_SEGLEN;
    const int colbase = b * (D * HW) + h * W + w;

    const float* __restrict__ p0 = g_bufB + 0 * NVOX;
    const float* __restrict__ p1 = g_bufB + 1 * NVOX;
    const float* __restrict__ p2 = g_bufB + 2 * NVOX;
    const float* __restrict__ p3 = g_bufB + 3 * NVOX;
    const float* __restrict__ p4 = g_bufB + 4 * NVOX;

    float s0 = 0.f, s1 = 0.f, s2 = 0.f, s3 = 0.f, s4 = 0.f;
    float acc = 0.f;
    float rg0[11], rg1[11], rg2[11], rg3[11], rg4[11];
    int r = d0 - 5;
    int t = 0;

#pragma unroll 1
    for (int tc = 0; tc < 4; tc++) {
        KB_STEP(0) KB_STEP(1) KB_STEP(2) KB_STEP(3) KB_STEP(4) KB_STEP(5)
        KB_STEP(6) KB_STEP(7) KB_STEP(8) KB_STEP(9) KB_STEP(10)
    }
    KB_STEP(0) KB_STEP(1) KB_STEP(2) KB_STEP(3) KB_STEP(4) KB_STEP(5)

    // deterministic block reduction over 160 threads
    red[w] = acc;
    __syncthreads();
    if (w < 80) red[w] += red[w + 80];
    __syncthreads();
    if (w < 40) red[w] += red[w + 40];
    __syncthreads();
    if (w < 20) red[w] += red[w + 20];
    __syncthreads();
    if (w < 10) red[w] += red[w + 10];
    __syncthreads();
    if (w < 5) red[w] += red[w + 5];
    __syncthreads();
    if (w == 0) {
        g_ssimpart[bid] = red[0] + red[1] + red[2] + red[3] + red[4];
    }
}
#undef KB_STEP

// ---------------------------------------------------------------------------
// Kernel C: final deterministic reduction.
// ---------------------------------------------------------------------------
__global__ __launch_bounds__(256) void kC_final(float* __restrict__ out) {
    __shared__ double sh[256];
    const int t = threadIdx.x;

    double a = 0.0;
    for (int i = t; i < A_BLOCKS; i += 256) a += (double)g_l1part[i];
    double bsum = 0.0;
    for (int i = t; i < K3_BLOCKS; i += 256) bsum += (double)g_ssimpart[i];

    sh[t] = a;
    __syncthreads();
#pragma unroll
    for (int s = 128; s > 0; s >>= 1) {
        if (t < s) sh[t] += sh[t + s];
        __syncthreads();
    }
    double l1sum = sh[0];
    __syncthreads();

    sh[t] = bsum;
    __syncthreads();
#pragma unroll
    for (int s = 128; s > 0; s >>= 1) {
        if (t < s) sh[t] += sh[t + s];
        __syncthreads();
    }

    if (t == 0) {
        double ssimsum = sh[0];
        double n = (double)NVOX;
        out[0] = (float)(0.85 * (ssimsum / n) + 0.15 * (l1sum / n));
    }
}

// ---------------------------------------------------------------------------
extern "C" void kernel_launch(void* const* d_in, const int* in_sizes, int n_in,
                              void* d_out, int out_size) {
    const float* pred = (const float*)d_in[0];
    const float* target = (const float*)d_in[1];
    float* out = (float*)d_out;

    kA_wh<<<A_BLOCKS, W>>>(pred, target);
    kB_dpass_ssim<<<K3_BLOCKS, W>>>();
    kC_final<<<1, 256>>>(out);
}

// round 6
// speedup vs baseline: 1.3449x; 1.3449x over previous
#include <cuda_runtime.h>

// Fixed shapes
#define B 2
#define D 160
#define H 160
#define W 160
#define NVOX (B * D * H * W)          // 8,192,000
#define HW (H * W)                    // 25,600

#define HSEGS 4
#define HSEG_LEN (H / HSEGS)          // 40
#define A_BLOCKS (B * D * HSEGS)      // 1280

#define KB_SEGS 5
#define KB_SEGLEN (D / KB_SEGS)       // 32
#define KB_HBLK 4
#define KB_THREADS 320                // 80 float2-lanes x 4 h-rows
#define KB_BLOCKS (B * (H / KB_HBLK) * KB_SEGS)  // 400

// SSIM constants (faithful: C1 = K1 / data_range^2)
#define C1F 5.9604644775390625e-10f   // 0.01 / 4096^2
#define C2F 1.7881393432617188e-09f   // 0.03 / 4096^2
#define INV_WIN3 (1.0f / 1331.0f)

__device__ float g_bufB[5 * NVOX];
__device__ float g_l1part[A_BLOCKS];
__device__ float g_ssimpart[KB_BLOCKS];

// ---------------------------------------------------------------------------
// Kernel A: fused W+H box sums (x, y, x^2, y^2, xy) streaming along h.
// Register ring (static indices via 11-step unroll), zero-padded smem staging,
// one barrier per row. UNCHANGED from R5 (measured 62.8us).
// ---------------------------------------------------------------------------
#define KA_STEP(TT) { \
    sx[buf][5 + w] = px; sy[buf][5 + w] = py; \
    const bool outl1 = (r >= h0) && (r < h1); \
    { int rn = r + 1; \
      if (rn >= 0 && rn < H) { px = x[pb + rn * W + w]; py = y[pb + rn * W + w]; } \
      else { px = 0.f; py = 0.f; } } \
    __syncthreads(); \
    { const float* __restrict__ rxp = sx[buf]; \
      const float* __restrict__ ryp = sy[buf]; \
      float ax = 0.f, ay = 0.f, axx = 0.f, ayy = 0.f, axy = 0.f; \
      _Pragma("unroll") \
      for (int jj = 0; jj < 11; jj++) { \
          float a = rxp[w + jj], c = ryp[w + jj]; \
          ax += a; ay += c; \
          axx = fmaf(a, a, axx); ayy = fmaf(c, c, ayy); axy = fmaf(a, c, axy); \
      } \
      rg0[TT] = ax; rg1[TT] = ay; rg2[TT] = axx; rg3[TT] = ayy; rg4[TT] = axy; \
      s0 += ax; s1 += ay; s2 += axx; s3 += ayy; s4 += axy; \
      if (outl1) { \
          float dd = fabsf(rxp[5 + w] - ryp[5 + w]); \
          l1acc += (dd < 1.f) ? 0.5f * dd * dd : dd - 0.5f; \
      } } \
    if (t >= 10) { \
        const int hh = h0 + t - 10; \
        const int oi = pb + hh * W + w; \
        g_bufB[0 * NVOX + oi] = s0; \
        g_bufB[1 * NVOX + oi] = s1; \
        g_bufB[2 * NVOX + oi] = s2; \
        g_bufB[3 * NVOX + oi] = s3; \
        g_bufB[4 * NVOX + oi] = s4; \
        s0 -= rg0[(TT + 1) % 11]; s1 -= rg1[(TT + 1) % 11]; \
        s2 -= rg2[(TT + 1) % 11]; s3 -= rg3[(TT + 1) % 11]; \
        s4 -= rg4[(TT + 1) % 11]; \
    } \
    buf ^= 1; r++; t++; }

__global__ __launch_bounds__(W, 4) void kA_wh(const float* __restrict__ x,
                                              const float* __restrict__ y) {
    __shared__ float sx[2][W + 10];
    __shared__ float sy[2][W + 10];

    const int bx = blockIdx.x;
    const int seg = bx % HSEGS;
    const int d = (bx / HSEGS) % D;
    const int b = bx / (HSEGS * D);
    const int w = threadIdx.x;

    const int h0 = seg * HSEG_LEN;
    const int h1 = h0 + HSEG_LEN;
    const int pb = (b * D + d) * HW;

    if (w < 10) {
        int p = (w < 5) ? w : (W + w);
        sx[0][p] = 0.f; sx[1][p] = 0.f;
        sy[0][p] = 0.f; sy[1][p] = 0.f;
    }

    int r = h0 - 5;
    float px = 0.f, py = 0.f;
    if (r >= 0) {
        px = x[pb + r * W + w];
        py = y[pb + r * W + w];
    }
    __syncthreads();

    float s0 = 0.f, s1 = 0.f, s2 = 0.f, s3 = 0.f, s4 = 0.f;
    float l1acc = 0.f;
    float rg0[11], rg1[11], rg2[11], rg3[11], rg4[11];
    int buf = 0;
    int t = 0;

#pragma unroll 1
    for (int tc = 0; tc < 4; tc++) {
        KA_STEP(0) KA_STEP(1) KA_STEP(2) KA_STEP(3) KA_STEP(4) KA_STEP(5)
        KA_STEP(6) KA_STEP(7) KA_STEP(8) KA_STEP(9) KA_STEP(10)
    }
    KA_STEP(0) KA_STEP(1) KA_STEP(2) KA_STEP(3) KA_STEP(4) KA_STEP(5)

    __syncthreads();
    float* red = sx[0];
    red[w] = l1acc;
    __syncthreads();
    if (w < 80) red[w] += red[w + 80];
    __syncthreads();
    if (w < 40) red[w] += red[w + 40];
    __syncthreads();
    if (w < 20) red[w] += red[w + 20];
    __syncthreads();
    if (w < 10) red[w] += red[w + 10];
    __syncthreads();
    if (w < 5) red[w] += red[w + 5];
    __syncthreads();
    if (w == 0) {
        g_l1part[bx] = red[0] + red[1] + red[2] + red[3] + red[4];
    }
}
#undef KA_STEP

// ---------------------------------------------------------------------------
// SSIM scalar helper
// ---------------------------------------------------------------------------
__device__ __forceinline__ float ssim_loss(float s0, float s1, float s2,
                                           float s3, float s4) {
    float mux = s0 * INV_WIN3;
    float muy = s1 * INV_WIN3;
    float mux2 = mux * mux;
    float muy2 = muy * muy;
    float muxy = mux * muy;
    float sxx = s2 * INV_WIN3 - mux2;
    float syy = s3 * INV_WIN3 - muy2;
    float sxy = s4 * INV_WIN3 - muxy;
    float num = (2.f * muxy + C1F) * (2.f * sxy + C2F);
    float den = (mux2 + muy2 + C1F) * (sxx + syy + C2F);
    float ssim = num / (den + 1e-8f);
    float loss = (1.f - ssim) * 0.5f;
    return fminf(fmaxf(loss, 0.f), 1.f);
}

// ---------------------------------------------------------------------------
// Kernel B: box-sum along D (running sums, leading+trailing edges; trailing
// hits L2) + SSIM + block reduction. float2 per thread, 4 h-rows per block.
// grid = B*(H/4)*KB_SEGS = 400 blocks, 320 threads.
// ---------------------------------------------------------------------------
__global__ __launch_bounds__(KB_THREADS) void kB_dpass_ssim() {
    __shared__ float red[KB_THREADS];

    const int bid = blockIdx.x;
    const int seg = bid % KB_SEGS;
    const int hq = (bid / KB_SEGS) % (H / KB_HBLK);
    const int b = bid / (KB_SEGS * (H / KB_HBLK));

    const int tid = threadIdx.x;
    const int w2 = tid % (W / 2);      // float2 lane
    const int hr = tid / (W / 2);      // 0..3
    const int h = hq * KB_HBLK + hr;

    const int d0 = seg * KB_SEGLEN;
    const int col2 = (b * (D * HW) + h * W) / 2 + w2;  // float2 index at d=0
    const int st2 = HW / 2;                             // float2 stride per d

    const float2* __restrict__ q0 = (const float2*)(g_bufB + 0 * NVOX);
    const float2* __restrict__ q1 = (const float2*)(g_bufB + 1 * NVOX);
    const float2* __restrict__ q2 = (const float2*)(g_bufB + 2 * NVOX);
    const float2* __restrict__ q3 = (const float2*)(g_bufB + 3 * NVOX);
    const float2* __restrict__ q4 = (const float2*)(g_bufB + 4 * NVOX);

    float2 s0 = {0.f, 0.f}, s1 = {0.f, 0.f}, s2 = {0.f, 0.f};
    float2 s3 = {0.f, 0.f}, s4 = {0.f, 0.f};
    {
        int lo = d0 - 5; if (lo < 0) lo = 0;
        int hi = d0 + 5; if (hi > D - 1) hi = D - 1;
        for (int d = lo; d <= hi; d++) {
            int id = col2 + d * st2;
            float2 v;
            v = q0[id]; s0.x += v.x; s0.y += v.y;
            v = q1[id]; s1.x += v.x; s1.y += v.y;
            v = q2[id]; s2.x += v.x; s2.y += v.y;
            v = q3[id]; s3.x += v.x; s3.y += v.y;
            v = q4[id]; s4.x += v.x; s4.y += v.y;
        }
    }

    float acc = 0.f;
#pragma unroll 4
    for (int i = 0; i < KB_SEGLEN; i++) {
        const int d = d0 + i;
        const int dn = d + 6;
        const int dp = d - 5;

        float2 a0 = {0.f, 0.f}, a1 = {0.f, 0.f}, a2 = {0.f, 0.f};
        float2 a3 = {0.f, 0.f}, a4 = {0.f, 0.f};
        float2 b0 = {0.f, 0.f}, b1 = {0.f, 0.f}, b2 = {0.f, 0.f};
        float2 b3 = {0.f, 0.f}, b4 = {0.f, 0.f};
        if (dn < D) {
            int id = col2 + dn * st2;
            a0 = q0[id]; a1 = q1[id]; a2 = q2[id]; a3 = q3[id]; a4 = q4[id];
        }
        if (dp >= 0) {
            int id = col2 + dp * st2;
            b0 = q0[id]; b1 = q1[id]; b2 = q2[id]; b3 = q3[id]; b4 = q4[id];
        }

        acc += ssim_loss(s0.x, s1.x, s2.x, s3.x, s4.x);
        acc += ssim_loss(s0.y, s1.y, s2.y, s3.y, s4.y);

        s0.x += a0.x - b0.x; s0.y += a0.y - b0.y;
        s1.x += a1.x - b1.x; s1.y += a1.y - b1.y;
        s2.x += a2.x - b2.x; s2.y += a2.y - b2.y;
        s3.x += a3.x - b3.x; s3.y += a3.y - b3.y;
        s4.x += a4.x - b4.x; s4.y += a4.y - b4.y;
    }

    // deterministic block reduction over 320 threads
    red[tid] = acc;
    __syncthreads();
    if (tid < 160) red[tid] += red[tid + 160];
    __syncthreads();
    if (tid < 80) red[tid] += red[tid + 80];
    __syncthreads();
    if (tid < 40) red[tid] += red[tid + 40];
    __syncthreads();
    if (tid < 20) red[tid] += red[tid + 20];
    __syncthreads();
    if (tid < 10) red[tid] += red[tid + 10];
    __syncthreads();
    if (tid < 5) red[tid] += red[tid + 5];
    __syncthreads();
    if (tid == 0) {
        g_ssimpart[bid] = red[0] + red[1] + red[2] + red[3] + red[4];
    }
}

// ---------------------------------------------------------------------------
// Kernel C: final deterministic reduction.
// ---------------------------------------------------------------------------
__global__ __launch_bounds__(256) void kC_final(float* __restrict__ out) {
    __shared__ double sh[256];
    const int t = threadIdx.x;

    double a = 0.0;
    for (int i = t; i < A_BLOCKS; i += 256) a += (double)g_l1part[i];
    double bsum = 0.0;
    for (int i = t; i < KB_BLOCKS; i += 256) bsum += (double)g_ssimpart[i];

    sh[t] = a;
    __syncthreads();
#pragma unroll
    for (int s = 128; s > 0; s >>= 1) {
        if (t < s) sh[t] += sh[t + s];
        __syncthreads();
    }
    double l1sum = sh[0];
    __syncthreads();

    sh[t] = bsum;
    __syncthreads();
#pragma unroll
    for (int s = 128; s > 0; s >>= 1) {
        if (t < s) sh[t] += sh[t + s];
        __syncthreads();
    }

    if (t == 0) {
        double ssimsum = sh[0];
        double n = (double)NVOX;
        out[0] = (float)(0.85 * (ssimsum / n) + 0.15 * (l1sum / n));
    }
}

// ---------------------------------------------------------------------------
extern "C" void kernel_launch(void* const* d_in, const int* in_sizes, int n_in,
                              void* d_out, int out_size) {
    const float* pred = (const float*)d_in[0];
    const float* target = (const float*)d_in[1];
    float* out = (float*)d_out;

    kA_wh<<<A_BLOCKS, W>>>(pred, target);
    kB_dpass_ssim<<<KB_BLOCKS, KB_THREADS>>>();
    kC_final<<<1, 256>>>(out);
}

// round 7
// speedup vs baseline: 1.4274x; 1.0614x over previous
#include <cuda_runtime.h>
#include <cstdint>

// Fixed shapes
#define B 2
#define D 160
#define H 160
#define W 160
#define NVOX (B * D * H * W)          // 8,192,000
#define HW (H * W)                    // 25,600

#define HSEGS 4
#define HSEG_LEN (H / HSEGS)          // 40
#define A_BLOCKS (B * D * HSEGS)      // 1280
#define KA_THREADS 80                 // one float2 (2 outputs) per thread
#define SROW 172                      // 6 pad + 160 + 6 pad

#define KB_SEGS 5
#define KB_SEGLEN (D / KB_SEGS)       // 32
#define KB_HBLK 2
#define KB_THREADS 160                // 80 float2-lanes x 2 h-rows
#define KB_BLOCKS (B * (H / KB_HBLK) * KB_SEGS)  // 800

// SSIM constants (faithful: C1 = K1 / data_range^2)
#define C1F 5.9604644775390625e-10f   // 0.01 / 4096^2
#define C2F 1.7881393432617188e-09f   // 0.03 / 4096^2
#define INV_WIN3 (1.0f / 1331.0f)

__device__ float g_bufB[5 * NVOX];
__device__ float g_l1part[A_BLOCKS];
__device__ float g_ssimpart[KB_BLOCKS];

__device__ __forceinline__ void cp_async8(uint32_t saddr, const void* g) {
    asm volatile("cp.async.ca.shared.global [%0], [%1], 8;" :: "r"(saddr), "l"(g));
}
__device__ __forceinline__ void cp_commit() {
    asm volatile("cp.async.commit_group;");
}
__device__ __forceinline__ void cp_wait2() {
    asm volatile("cp.async.wait_group 2;");
}

// ---------------------------------------------------------------------------
// Kernel A: fused W+H box sums (x, y, x^2, y^2, xy), 2 outputs per thread.
// 11-slot cp.async staging pipeline (depth 3), float2 taps, incremental
// second output, register ring (float2 x 5 x 11) for the h running sums.
// grid = B*D*HSEGS, 80 threads.
// ---------------------------------------------------------------------------
#define KA_FETCH(ROW, SLOT) { \
    const int _r = (ROW); \
    if (_r >= 0 && _r < H) { \
        cp_async8(sx_base + (SLOT) * (SROW * 4) + (6 + w) * 4, x + pb + _r * W + w); \
        cp_async8(sy_base + (SLOT) * (SROW * 4) + (6 + w) * 4, y + pb + _r * W + w); \
    } else { \
        *(float2*)&sx[SLOT][6 + w] = make_float2(0.f, 0.f); \
        *(float2*)&sy[SLOT][6 + w] = make_float2(0.f, 0.f); \
    } \
    cp_commit(); }

#define KA_STEP(TT) { \
    cp_wait2(); \
    __syncthreads(); \
    { \
        const float2* rx2 = (const float2*)&sx[TT][w]; \
        const float2* ry2 = (const float2*)&sy[TT][w]; \
        float xv[14], yv[14]; \
        _Pragma("unroll") \
        for (int i = 0; i < 7; i++) { \
            float2 t2 = rx2[i]; xv[2*i] = t2.x; xv[2*i+1] = t2.y; \
            float2 u2 = ry2[i]; yv[2*i] = u2.x; yv[2*i+1] = u2.y; \
        } \
        float ax = xv[1], ay = yv[1]; \
        float axx = xv[1]*xv[1], ayy = yv[1]*yv[1], axy = xv[1]*yv[1]; \
        _Pragma("unroll") \
        for (int i = 2; i <= 11; i++) { \
            ax += xv[i]; ay += yv[i]; \
            axx = fmaf(xv[i], xv[i], axx); \
            ayy = fmaf(yv[i], yv[i], ayy); \
            axy = fmaf(xv[i], yv[i], axy); \
        } \
        float dax = xv[12] - xv[1], day = yv[12] - yv[1]; \
        float ax1 = ax + dax, ay1 = ay + day; \
        float axx1 = fmaf(dax, xv[12] + xv[1], axx); \
        float ayy1 = fmaf(day, yv[12] + yv[1], ayy); \
        float axy1 = fmaf(-xv[1], yv[1], fmaf(xv[12], yv[12], axy)); \
        rg0[TT] = make_float2(ax, ax1);   s0.x += ax;  s0.y += ax1; \
        rg1[TT] = make_float2(ay, ay1);   s1.x += ay;  s1.y += ay1; \
        rg2[TT] = make_float2(axx, axx1); s2.x += axx; s2.y += axx1; \
        rg3[TT] = make_float2(ayy, ayy1); s3.x += ayy; s3.y += ayy1; \
        rg4[TT] = make_float2(axy, axy1); s4.x += axy; s4.y += axy1; \
        if (r >= h0 && r < h1) { \
            float e0 = fabsf(xv[6] - yv[6]); \
            l1acc += (e0 < 1.f) ? 0.5f * e0 * e0 : e0 - 0.5f; \
            float e1 = fabsf(xv[7] - yv[7]); \
            l1acc += (e1 < 1.f) ? 0.5f * e1 * e1 : e1 - 0.5f; \
        } \
    } \
    KA_FETCH(r + 3, (TT + 3) % 11) \
    if (t >= 10) { \
        const int hh = h0 + t - 10; \
        const int o2 = (pb + hh * W + w) >> 1; \
        float2* ob = (float2*)g_bufB; \
        ob[0 * (NVOX/2) + o2] = s0; \
        ob[1 * (NVOX/2) + o2] = s1; \
        ob[2 * (NVOX/2) + o2] = s2; \
        ob[3 * (NVOX/2) + o2] = s3; \
        ob[4 * (NVOX/2) + o2] = s4; \
        float2 z; \
        z = rg0[(TT + 1) % 11]; s0.x -= z.x; s0.y -= z.y; \
        z = rg1[(TT + 1) % 11]; s1.x -= z.x; s1.y -= z.y; \
        z = rg2[(TT + 1) % 11]; s2.x -= z.x; s2.y -= z.y; \
        z = rg3[(TT + 1) % 11]; s3.x -= z.x; s3.y -= z.y; \
        z = rg4[(TT + 1) % 11]; s4.x -= z.x; s4.y -= z.y; \
    } \
    r++; t++; }

__global__ __launch_bounds__(KA_THREADS, 4) void kA_wh(const float* __restrict__ x,
                                                       const float* __restrict__ y) {
    __shared__ __align__(16) float sx[11][SROW];
    __shared__ __align__(16) float sy[11][SROW];
    __shared__ float red[KA_THREADS];

    const int bx = blockIdx.x;
    const int seg = bx % HSEGS;
    const int d = (bx / HSEGS) % D;
    const int b = bx / (HSEGS * D);
    const int w2 = threadIdx.x;        // 0..79
    const int w = 2 * w2;

    const int h0 = seg * HSEG_LEN;
    const int h1 = h0 + HSEG_LEN;
    const int pb = (b * D + d) * HW;

    const uint32_t sx_base = (uint32_t)__cvta_generic_to_shared(&sx[0][0]);
    const uint32_t sy_base = (uint32_t)__cvta_generic_to_shared(&sy[0][0]);

    // zero pads once (cp.async never touches indices 0..5 / 166..171)
    if (w2 < 12) {
        int p = (w2 < 6) ? w2 : (160 + w2);
#pragma unroll
        for (int s = 0; s < 11; s++) { sx[s][p] = 0.f; sy[s][p] = 0.f; }
    }

    // prologue: fetch rows h0-5 .. h0-3 into slots 0..2
    KA_FETCH(h0 - 5, 0)
    KA_FETCH(h0 - 4, 1)
    KA_FETCH(h0 - 3, 2)

    float2 s0 = {0.f, 0.f}, s1 = {0.f, 0.f}, s2 = {0.f, 0.f};
    float2 s3 = {0.f, 0.f}, s4 = {0.f, 0.f};
    float l1acc = 0.f;
    float2 rg0[11], rg1[11], rg2[11], rg3[11], rg4[11];
    int r = h0 - 5;
    int t = 0;

#pragma unroll 1
    for (int tc = 0; tc < 4; tc++) {
        KA_STEP(0) KA_STEP(1) KA_STEP(2) KA_STEP(3) KA_STEP(4) KA_STEP(5)
        KA_STEP(6) KA_STEP(7) KA_STEP(8) KA_STEP(9) KA_STEP(10)
    }
    KA_STEP(0) KA_STEP(1) KA_STEP(2) KA_STEP(3) KA_STEP(4) KA_STEP(5)

    // deterministic block reduction of l1acc over 80 threads
    red[w2] = l1acc;
    __syncthreads();
    if (w2 < 40) red[w2] += red[w2 + 40];
    __syncthreads();
    if (w2 < 20) red[w2] += red[w2 + 20];
    __syncthreads();
    if (w2 < 10) red[w2] += red[w2 + 10];
    __syncthreads();
    if (w2 < 5) red[w2] += red[w2 + 5];
    __syncthreads();
    if (w2 == 0) {
        g_l1part[bx] = red[0] + red[1] + red[2] + red[3] + red[4];
    }
}
#undef KA_STEP
#undef KA_FETCH

// ---------------------------------------------------------------------------
// SSIM scalar helper
// ---------------------------------------------------------------------------
__device__ __forceinline__ float ssim_loss(float s0, float s1, float s2,
                                           float s3, float s4) {
    float mux = s0 * INV_WIN3;
    float muy = s1 * INV_WIN3;
    float mux2 = mux * mux;
    float muy2 = muy * muy;
    float muxy = mux * muy;
    float sxx = s2 * INV_WIN3 - mux2;
    float syy = s3 * INV_WIN3 - muy2;
    float sxy = s4 * INV_WIN3 - muxy;
    float num = (2.f * muxy + C1F) * (2.f * sxy + C2F);
    float den = (mux2 + muy2 + C1F) * (sxx + syy + C2F);
    float ssim = num / (den + 1e-8f);
    float loss = (1.f - ssim) * 0.5f;
    return fminf(fmaxf(loss, 0.f), 1.f);
}

// ---------------------------------------------------------------------------
// Kernel B: box-sum along D (running sums, leading+trailing edges; trailing
// hits L2) + SSIM + block reduction. float2 per thread, 2 h-rows per block.
// grid = B*(H/2)*KB_SEGS = 800 blocks, 160 threads.
// ---------------------------------------------------------------------------
__global__ __launch_bounds__(KB_THREADS) void kB_dpass_ssim() {
    __shared__ float red[KB_THREADS];

    const int bid = blockIdx.x;
    const int seg = bid % KB_SEGS;
    const int hq = (bid / KB_SEGS) % (H / KB_HBLK);
    const int b = bid / (KB_SEGS * (H / KB_HBLK));

    const int tid = threadIdx.x;
    const int w2 = tid % (W / 2);
    const int hr = tid / (W / 2);      // 0..1
    const int h = hq * KB_HBLK + hr;

    const int d0 = seg * KB_SEGLEN;
    const int col2 = (b * (D * HW) + h * W) / 2 + w2;
    const int st2 = HW / 2;

    const float2* __restrict__ q0 = (const float2*)(g_bufB + 0 * NVOX);
    const float2* __restrict__ q1 = (const float2*)(g_bufB + 1 * NVOX);
    const float2* __restrict__ q2 = (const float2*)(g_bufB + 2 * NVOX);
    const float2* __restrict__ q3 = (const float2*)(g_bufB + 3 * NVOX);
    const float2* __restrict__ q4 = (const float2*)(g_bufB + 4 * NVOX);

    float2 s0 = {0.f, 0.f}, s1 = {0.f, 0.f}, s2 = {0.f, 0.f};
    float2 s3 = {0.f, 0.f}, s4 = {0.f, 0.f};
    {
        int lo = d0 - 5; if (lo < 0) lo = 0;
        int hi = d0 + 5; if (hi > D - 1) hi = D - 1;
        for (int d = lo; d <= hi; d++) {
            int id = col2 + d * st2;
            float2 v;
            v = q0[id]; s0.x += v.x; s0.y += v.y;
            v = q1[id]; s1.x += v.x; s1.y += v.y;
            v = q2[id]; s2.x += v.x; s2.y += v.y;
            v = q3[id]; s3.x += v.x; s3.y += v.y;
            v = q4[id]; s4.x += v.x; s4.y += v.y;
        }
    }

    float acc = 0.f;
#pragma unroll 4
    for (int i = 0; i < KB_SEGLEN; i++) {
        const int d = d0 + i;
        const int dn = d + 6;
        const int dp = d - 5;

        float2 a0 = {0.f, 0.f}, a1 = {0.f, 0.f}, a2 = {0.f, 0.f};
        float2 a3 = {0.f, 0.f}, a4 = {0.f, 0.f};
        float2 b0 = {0.f, 0.f}, b1 = {0.f, 0.f}, b2 = {0.f, 0.f};
        float2 b3 = {0.f, 0.f}, b4 = {0.f, 0.f};
        if (dn < D) {
            int id = col2 + dn * st2;
            a0 = q0[id]; a1 = q1[id]; a2 = q2[id]; a3 = q3[id]; a4 = q4[id];
        }
        if (dp >= 0) {
            int id = col2 + dp * st2;
            b0 = q0[id]; b1 = q1[id]; b2 = q2[id]; b3 = q3[id]; b4 = q4[id];
        }

        acc += ssim_loss(s0.x, s1.x, s2.x, s3.x, s4.x);
        acc += ssim_loss(s0.y, s1.y, s2.y, s3.y, s4.y);

        s0.x += a0.x - b0.x; s0.y += a0.y - b0.y;
        s1.x += a1.x - b1.x; s1.y += a1.y - b1.y;
        s2.x += a2.x - b2.x; s2.y += a2.y - b2.y;
        s3.x += a3.x - b3.x; s3.y += a3.y - b3.y;
        s4.x += a4.x - b4.x; s4.y += a4.y - b4.y;
    }

    // deterministic block reduction over 160 threads
    red[tid] = acc;
    __syncthreads();
    if (tid < 80) red[tid] += red[tid + 80];
    __syncthreads();
    if (tid < 40) red[tid] += red[tid + 40];
    __syncthreads();
    if (tid < 20) red[tid] += red[tid + 20];
    __syncthreads();
    if (tid < 10) red[tid] += red[tid + 10];
    __syncthreads();
    if (tid < 5) red[tid] += red[tid + 5];
    __syncthreads();
    if (tid == 0) {
        g_ssimpart[bid] = red[0] + red[1] + red[2] + red[3] + red[4];
    }
}

// ---------------------------------------------------------------------------
// Kernel C: final deterministic reduction.
// ---------------------------------------------------------------------------
__global__ __launch_bounds__(256) void kC_final(float* __restrict__ out) {
    __shared__ double sh[256];
    const int t = threadIdx.x;

    double a = 0.0;
    for (int i = t; i < A_BLOCKS; i += 256) a += (double)g_l1part[i];
    double bsum = 0.0;
    for (int i = t; i < KB_BLOCKS; i += 256) bsum += (double)g_ssimpart[i];

    sh[t] = a;
    __syncthreads();
#pragma unroll
    for (int s = 128; s > 0; s >>= 1) {
        if (t < s) sh[t] += sh[t + s];
        __syncthreads();
    }
    double l1sum = sh[0];
    __syncthreads();

    sh[t] = bsum;
    __syncthreads();
#pragma unroll
    for (int s = 128; s > 0; s >>= 1) {
        if (t < s) sh[t] += sh[t + s];
        __syncthreads();
    }

    if (t == 0) {
        double ssimsum = sh[0];
        double n = (double)NVOX;
        out[0] = (float)(0.85 * (ssimsum / n) + 0.15 * (l1sum / n));
    }
}

// ---------------------------------------------------------------------------
extern "C" void kernel_launch(void* const* d_in, const int* in_sizes, int n_in,
                              void* d_out, int out_size) {
    const float* pred = (const float*)d_in[0];
    const float* target = (const float*)d_in[1];
    float* out = (float*)d_out;

    kA_wh<<<A_BLOCKS, KA_THREADS>>>(pred, target);
    kB_dpass_ssim<<<KB_BLOCKS, KB_THREADS>>>();
    kC_final<<<1, 256>>>(out);
}

// round 8
// speedup vs baseline: 1.7745x; 1.2432x over previous
#include <cuda_runtime.h>
#include <cuda_fp16.h>
#include <cstdint>

// Fixed shapes
#define B 2
#define D 160
#define H 160
#define W 160
#define NVOX (B * D * H * W)          // 8,192,000
#define HW (H * W)                    // 25,600

#define HSEGS 4
#define HSEG_LEN (H / HSEGS)          // 40
#define A_BLOCKS (B * D * HSEGS)      // 1280
#define KA_THREADS 80                 // one float2 (2 outputs) per thread
#define SROW 172                      // 6 pad + 160 + 6 pad

#define KB_SEGS 5
#define KB_SEGLEN (D / KB_SEGS)       // 32
#define KB_HBLK 2
#define KB_THREADS 160                // 80 half2-lanes x 2 h-rows
#define KB_BLOCKS (B * (H / KB_HBLK) * KB_SEGS)  // 800

// SSIM constants (faithful: C1 = K1 / data_range^2)
#define C1F 5.9604644775390625e-10f   // 0.01 / 4096^2
#define C2F 1.7881393432617188e-09f   // 0.03 / 4096^2
#define INV_WIN3 (1.0f / 1331.0f)

// Intermediate: 5 quantity planes, fp16 packed as half2 (w-pairs).
__device__ __half2 g_bufB[5 * (NVOX / 2)];
__device__ float g_l1part[A_BLOCKS];
__device__ float g_ssimpart[KB_BLOCKS];

__device__ __forceinline__ void cp_async8(uint32_t saddr, const void* g) {
    asm volatile("cp.async.ca.shared.global [%0], [%1], 8;" :: "r"(saddr), "l"(g));
}
__device__ __forceinline__ void cp_commit() {
    asm volatile("cp.async.commit_group;");
}
__device__ __forceinline__ void cp_wait2() {
    asm volatile("cp.async.wait_group 2;");
}

// ---------------------------------------------------------------------------
// Kernel A: fused W+H box sums (x, y, x^2, y^2, xy), 2 outputs per thread.
// 11-slot cp.async staging pipeline (depth 3), float2 taps, incremental
// second output, register ring. Output stored as half2.
// grid = B*D*HSEGS, 80 threads.
// ---------------------------------------------------------------------------
#define KA_FETCH(ROW, SLOT) { \
    const int _r = (ROW); \
    if (_r >= 0 && _r < H) { \
        cp_async8(sx_base + (SLOT) * (SROW * 4) + (6 + w) * 4, x + pb + _r * W + w); \
        cp_async8(sy_base + (SLOT) * (SROW * 4) + (6 + w) * 4, y + pb + _r * W + w); \
    } else { \
        *(float2*)&sx[SLOT][6 + w] = make_float2(0.f, 0.f); \
        *(float2*)&sy[SLOT][6 + w] = make_float2(0.f, 0.f); \
    } \
    cp_commit(); }

#define KA_STEP(TT) { \
    cp_wait2(); \
    __syncthreads(); \
    { \
        const float2* rx2 = (const float2*)&sx[TT][w]; \
        const float2* ry2 = (const float2*)&sy[TT][w]; \
        float xv[14], yv[14]; \
        _Pragma("unroll") \
        for (int i = 0; i < 7; i++) { \
            float2 t2 = rx2[i]; xv[2*i] = t2.x; xv[2*i+1] = t2.y; \
            float2 u2 = ry2[i]; yv[2*i] = u2.x; yv[2*i+1] = u2.y; \
        } \
        float ax = xv[1], ay = yv[1]; \
        float axx = xv[1]*xv[1], ayy = yv[1]*yv[1], axy = xv[1]*yv[1]; \
        _Pragma("unroll") \
        for (int i = 2; i <= 11; i++) { \
            ax += xv[i]; ay += yv[i]; \
            axx = fmaf(xv[i], xv[i], axx); \
            ayy = fmaf(yv[i], yv[i], ayy); \
            axy = fmaf(xv[i], yv[i], axy); \
        } \
        float dax = xv[12] - xv[1], day = yv[12] - yv[1]; \
        float ax1 = ax + dax, ay1 = ay + day; \
        float axx1 = fmaf(dax, xv[12] + xv[1], axx); \
        float ayy1 = fmaf(day, yv[12] + yv[1], ayy); \
        float axy1 = fmaf(-xv[1], yv[1], fmaf(xv[12], yv[12], axy)); \
        rg0[TT] = make_float2(ax, ax1);   s0.x += ax;  s0.y += ax1; \
        rg1[TT] = make_float2(ay, ay1);   s1.x += ay;  s1.y += ay1; \
        rg2[TT] = make_float2(axx, axx1); s2.x += axx; s2.y += axx1; \
        rg3[TT] = make_float2(ayy, ayy1); s3.x += ayy; s3.y += ayy1; \
        rg4[TT] = make_float2(axy, axy1); s4.x += axy; s4.y += axy1; \
        if (r >= h0 && r < h1) { \
            float e0 = fabsf(xv[6] - yv[6]); \
            l1acc += (e0 < 1.f) ? 0.5f * e0 * e0 : e0 - 0.5f; \
            float e1 = fabsf(xv[7] - yv[7]); \
            l1acc += (e1 < 1.f) ? 0.5f * e1 * e1 : e1 - 0.5f; \
        } \
    } \
    KA_FETCH(r + 3, (TT + 3) % 11) \
    if (t >= 10) { \
        const int hh = h0 + t - 10; \
        const int o2 = (pb + hh * W + w) >> 1; \
        g_bufB[0 * (NVOX/2) + o2] = __float22half2_rn(s0); \
        g_bufB[1 * (NVOX/2) + o2] = __float22half2_rn(s1); \
        g_bufB[2 * (NVOX/2) + o2] = __float22half2_rn(s2); \
        g_bufB[3 * (NVOX/2) + o2] = __float22half2_rn(s3); \
        g_bufB[4 * (NVOX/2) + o2] = __float22half2_rn(s4); \
        float2 z; \
        z = rg0[(TT + 1) % 11]; s0.x -= z.x; s0.y -= z.y; \
        z = rg1[(TT + 1) % 11]; s1.x -= z.x; s1.y -= z.y; \
        z = rg2[(TT + 1) % 11]; s2.x -= z.x; s2.y -= z.y; \
        z = rg3[(TT + 1) % 11]; s3.x -= z.x; s3.y -= z.y; \
        z = rg4[(TT + 1) % 11]; s4.x -= z.x; s4.y -= z.y; \
    } \
    r++; t++; }

__global__ __launch_bounds__(KA_THREADS, 4) void kA_wh(const float* __restrict__ x,
                                                       const float* __restrict__ y) {
    __shared__ __align__(16) float sx[11][SROW];
    __shared__ __align__(16) float sy[11][SROW];
    __shared__ float red[KA_THREADS];

    const int bx = blockIdx.x;
    const int seg = bx % HSEGS;
    const int d = (bx / HSEGS) % D;
    const int b = bx / (HSEGS * D);
    const int w2 = threadIdx.x;        // 0..79
    const int w = 2 * w2;

    const int h0 = seg * HSEG_LEN;
    const int h1 = h0 + HSEG_LEN;
    const int pb = (b * D + d) * HW;

    const uint32_t sx_base = (uint32_t)__cvta_generic_to_shared(&sx[0][0]);
    const uint32_t sy_base = (uint32_t)__cvta_generic_to_shared(&sy[0][0]);

    // zero pads once (cp.async never touches indices 0..5 / 166..171)
    if (w2 < 12) {
        int p = (w2 < 6) ? w2 : (160 + w2);
#pragma unroll
        for (int s = 0; s < 11; s++) { sx[s][p] = 0.f; sy[s][p] = 0.f; }
    }

    // prologue: fetch rows h0-5 .. h0-3 into slots 0..2
    KA_FETCH(h0 - 5, 0)
    KA_FETCH(h0 - 4, 1)
    KA_FETCH(h0 - 3, 2)

    float2 s0 = {0.f, 0.f}, s1 = {0.f, 0.f}, s2 = {0.f, 0.f};
    float2 s3 = {0.f, 0.f}, s4 = {0.f, 0.f};
    float l1acc = 0.f;
    float2 rg0[11], rg1[11], rg2[11], rg3[11], rg4[11];
    int r = h0 - 5;
    int t = 0;

#pragma unroll 1
    for (int tc = 0; tc < 4; tc++) {
        KA_STEP(0) KA_STEP(1) KA_STEP(2) KA_STEP(3) KA_STEP(4) KA_STEP(5)
        KA_STEP(6) KA_STEP(7) KA_STEP(8) KA_STEP(9) KA_STEP(10)
    }
    KA_STEP(0) KA_STEP(1) KA_STEP(2) KA_STEP(3) KA_STEP(4) KA_STEP(5)

    // deterministic block reduction of l1acc over 80 threads
    red[w2] = l1acc;
    __syncthreads();
    if (w2 < 40) red[w2] += red[w2 + 40];
    __syncthreads();
    if (w2 < 20) red[w2] += red[w2 + 20];
    __syncthreads();
    if (w2 < 10) red[w2] += red[w2 + 10];
    __syncthreads();
    if (w2 < 5) red[w2] += red[w2 + 5];
    __syncthreads();
    if (w2 == 0) {
        g_l1part[bx] = red[0] + red[1] + red[2] + red[3] + red[4];
    }
}
#undef KA_STEP
#undef KA_FETCH

// ---------------------------------------------------------------------------
// SSIM scalar helper
// ---------------------------------------------------------------------------
__device__ __forceinline__ float ssim_loss(float s0, float s1, float s2,
                                           float s3, float s4) {
    float mux = s0 * INV_WIN3;
    float muy = s1 * INV_WIN3;
    float mux2 = mux * mux;
    float muy2 = muy * muy;
    float muxy = mux * muy;
    float sxx = s2 * INV_WIN3 - mux2;
    float syy = s3 * INV_WIN3 - muy2;
    float sxy = s4 * INV_WIN3 - muxy;
    float num = (2.f * muxy + C1F) * (2.f * sxy + C2F);
    float den = (mux2 + muy2 + C1F) * (sxx + syy + C2F);
    float ssim = num / (den + 1e-8f);
    float loss = (1.f - ssim) * 0.5f;
    return fminf(fmaxf(loss, 0.f), 1.f);
}

// ---------------------------------------------------------------------------
// Kernel B: box-sum along D (running sums, leading+trailing edges) + SSIM +
// block reduction. half2 per thread, 2 h-rows per block.
// grid = B*(H/2)*KB_SEGS = 800 blocks, 160 threads.
// ---------------------------------------------------------------------------
__global__ __launch_bounds__(KB_THREADS) void kB_dpass_ssim() {
    __shared__ float red[KB_THREADS];

    const int bid = blockIdx.x;
    const int seg = bid % KB_SEGS;
    const int hq = (bid / KB_SEGS) % (H / KB_HBLK);
    const int b = bid / (KB_SEGS * (H / KB_HBLK));

    const int tid = threadIdx.x;
    const int w2 = tid % (W / 2);
    const int hr = tid / (W / 2);      // 0..1
    const int h = hq * KB_HBLK + hr;

    const int d0 = seg * KB_SEGLEN;
    const int col2 = (b * (D * HW) + h * W) / 2 + w2;
    const int st2 = HW / 2;

    const __half2* __restrict__ q0 = g_bufB + 0 * (NVOX / 2);
    const __half2* __restrict__ q1 = g_bufB + 1 * (NVOX / 2);
    const __half2* __restrict__ q2 = g_bufB + 2 * (NVOX / 2);
    const __half2* __restrict__ q3 = g_bufB + 3 * (NVOX / 2);
    const __half2* __restrict__ q4 = g_bufB + 4 * (NVOX / 2);

    float2 s0 = {0.f, 0.f}, s1 = {0.f, 0.f}, s2 = {0.f, 0.f};
    float2 s3 = {0.f, 0.f}, s4 = {0.f, 0.f};
    {
        int lo = d0 - 5; if (lo < 0) lo = 0;
        int hi = d0 + 5; if (hi > D - 1) hi = D - 1;
        for (int d = lo; d <= hi; d++) {
            int id = col2 + d * st2;
            float2 v;
            v = __half22float2(q0[id]); s0.x += v.x; s0.y += v.y;
            v = __half22float2(q1[id]); s1.x += v.x; s1.y += v.y;
            v = __half22float2(q2[id]); s2.x += v.x; s2.y += v.y;
            v = __half22float2(q3[id]); s3.x += v.x; s3.y += v.y;
            v = __half22float2(q4[id]); s4.x += v.x; s4.y += v.y;
        }
    }

    float acc = 0.f;
#pragma unroll 4
    for (int i = 0; i < KB_SEGLEN; i++) {
        const int d = d0 + i;
        const int dn = d + 6;
        const int dp = d - 5;

        float2 a0 = {0.f, 0.f}, a1 = {0.f, 0.f}, a2 = {0.f, 0.f};
        float2 a3 = {0.f, 0.f}, a4 = {0.f, 0.f};
        float2 b0 = {0.f, 0.f}, b1 = {0.f, 0.f}, b2 = {0.f, 0.f};
        float2 b3 = {0.f, 0.f}, b4 = {0.f, 0.f};
        if (dn < D) {
            int id = col2 + dn * st2;
            a0 = __half22float2(q0[id]); a1 = __half22float2(q1[id]);
            a2 = __half22float2(q2[id]); a3 = __half22float2(q3[id]);
            a4 = __half22float2(q4[id]);
        }
        if (dp >= 0) {
            int id = col2 + dp * st2;
            b0 = __half22float2(q0[id]); b1 = __half22float2(q1[id]);
            b2 = __half22float2(q2[id]); b3 = __half22float2(q3[id]);
            b4 = __half22float2(q4[id]);
        }

        acc += ssim_loss(s0.x, s1.x, s2.x, s3.x, s4.x);
        acc += ssim_loss(s0.y, s1.y, s2.y, s3.y, s4.y);

        s0.x += a0.x - b0.x; s0.y += a0.y - b0.y;
        s1.x += a1.x - b1.x; s1.y += a1.y - b1.y;
        s2.x += a2.x - b2.x; s2.y += a2.y - b2.y;
        s3.x += a3.x - b3.x; s3.y += a3.y - b3.y;
        s4.x += a4.x - b4.x; s4.y += a4.y - b4.y;
    }

    // deterministic block reduction over 160 threads
    red[tid] = acc;
    __syncthreads();
    if (tid < 80) red[tid] += red[tid + 80];
    __syncthreads();
    if (tid < 40) red[tid] += red[tid + 40];
    __syncthreads();
    if (tid < 20) red[tid] += red[tid + 20];
    __syncthreads();
    if (tid < 10) red[tid] += red[tid + 10];
    __syncthreads();
    if (tid < 5) red[tid] += red[tid + 5];
    __syncthreads();
    if (tid == 0) {
        g_ssimpart[bid] = red[0] + red[1] + red[2] + red[3] + red[4];
    }
}

// ---------------------------------------------------------------------------
// Kernel C: final deterministic reduction.
// ---------------------------------------------------------------------------
__global__ __launch_bounds__(256) void kC_final(float* __restrict__ out) {
    __shared__ double sh[256];
    const int t = threadIdx.x;

    double a = 0.0;
    for (int i = t; i < A_BLOCKS; i += 256) a += (double)g_l1part[i];
    double bsum = 0.0;
    for (int i = t; i < KB_BLOCKS; i += 256) bsum += (double)g_ssimpart[i];

    sh[t] = a;
    __syncthreads();
#pragma unroll
    for (int s = 128; s > 0; s >>= 1) {
        if (t < s) sh[t] += sh[t + s];
        __syncthreads();
    }
    double l1sum = sh[0];
    __syncthreads();

    sh[t] = bsum;
    __syncthreads();
#pragma unroll
    for (int s = 128; s > 0; s >>= 1) {
        if (t < s) sh[t] += sh[t + s];
        __syncthreads();
    }

    if (t == 0) {
        double ssimsum = sh[0];
        double n = (double)NVOX;
        out[0] = (float)(0.85 * (ssimsum / n) + 0.15 * (l1sum / n));
    }
}

// ---------------------------------------------------------------------------
extern "C" void kernel_launch(void* const* d_in, const int* in_sizes, int n_in,
                              void* d_out, int out_size) {
    const float* pred = (const float*)d_in[0];
    const float* target = (const float*)d_in[1];
    float* out = (float*)d_out;

    kA_wh<<<A_BLOCKS, KA_THREADS>>>(pred, target);
    kB_dpass_ssim<<<KB_BLOCKS, KB_THREADS>>>();
    kC_final<<<1, 256>>>(out);
}